// round 2
// baseline (speedup 1.0000x reference)
#include <cuda_runtime.h>
#include <cuda_bf16.h>

// GCNLayer SpMM: out[i,:] = sum_{e: rows[e]==i} vals[e] * embeds[cols[e],:]
// N=10000 nodes, E=640000 edges, D=128 features.
//
// Round-0 design: warp-per-edge gather (float4/lane) + vectorized
// red.global.add.v4.f32 scatter. Entire working set (~18MB) is L2-resident,
// so the bound is L2 traffic: ~655MB -> ~60us floor.

static constexpr int D_FEAT = 128;
static constexpr int D_VEC  = D_FEAT / 4;   // 32 float4 per row = 1 per lane

__global__ void zero_out_kernel(float4* __restrict__ out, int n4) {
    int i = blockIdx.x * blockDim.x + threadIdx.x;
    if (i < n4) out[i] = make_float4(0.f, 0.f, 0.f, 0.f);
}

__global__ __launch_bounds__(256) void spmm_atomic_kernel(
    const int*    __restrict__ rows,
    const int*    __restrict__ cols,
    const float*  __restrict__ vals,
    const float4* __restrict__ emb,    // [N, 32] float4
    float4*       __restrict__ out,    // [N, 32] float4
    int E)
{
    int gid  = blockIdx.x * blockDim.x + threadIdx.x;
    int e    = gid >> 5;
    int lane = gid & 31;
    if (e >= E) return;

    int   r = __ldg(rows + e);
    int   c = __ldg(cols + e);
    float v = __ldg(vals + e);

    float4 x = __ldg(emb + c * D_VEC + lane);

    float4* dst = out + r * D_VEC + lane;
    asm volatile(
        "red.global.add.v4.f32 [%0], {%1, %2, %3, %4};"
        :: "l"(dst), "f"(v * x.x), "f"(v * x.y), "f"(v * x.z), "f"(v * x.w)
        : "memory");
}

extern "C" void kernel_launch(void* const* d_in, const int* in_sizes, int n_in,
                              void* d_out, int out_size) {
    const int*   adj_rows = (const int*)  d_in[0];
    const int*   adj_cols = (const int*)  d_in[1];
    const float* adj_vals = (const float*)d_in[2];
    const float* embeds   = (const float*)d_in[3];
    float*       out      = (float*)d_out;

    const int E = in_sizes[0];          // 640000
    const int n4 = out_size / 4;        // 1280000/4 = 320000 float4

    {
        int threads = 256;
        int blocks  = (n4 + threads - 1) / threads;
        zero_out_kernel<<<blocks, threads>>>((float4*)out, n4);
    }
    {
        int threads = 256;                    // 8 warps = 8 edges per block
        long long total_threads = (long long)E * 32;
        int blocks = (int)((total_threads + threads - 1) / threads);
        spmm_atomic_kernel<<<blocks, threads>>>(
            adj_rows, adj_cols, adj_vals,
            (const float4*)embeds, (float4*)out, E);
    }
}

// round 3
// speedup vs baseline: 1.0354x; 1.0354x over previous
#include <cuda_runtime.h>
#include <cuda_bf16.h>

// GCNLayer SpMM: out[i,:] = sum_{e: rows[e]==i} vals[e] * embeds[cols[e],:]
// N=10000 nodes, E=640000 edges, D=128 features.
//
// Round-2 design: the round-0 atomic kernel was bound by the L2 atomic ALUs
// (20.5M RED.128 ops ~= 60us of per-slice serialization). Convert scatter ->
// gather: counting-sort edges by row into __device__ scratch (packed
// (col,val) pairs), then warp-per-row CSR SpMM with register accumulation and
// a single STG.128 per lane. Main pass has ZERO atomics and ~345MB of
// L2-resident reads -> ~30us; preprocessing ~15us.

static constexpr int MAX_N = 10000;
static constexpr int MAX_E = 640000;
static constexpr int D_VEC = 32;           // 128 floats = 32 float4 per row

__device__ int   g_count[MAX_N];
__device__ int   g_start[MAX_N + 1];
__device__ int   g_cursor[MAX_N];
__device__ uint2 g_pairs[MAX_E];           // .x = col, .y = bits(val), row-sorted

// ---------------------------------------------------------------- kernel 1
__global__ void zero_counts_kernel(int n) {
    int i = blockIdx.x * blockDim.x + threadIdx.x;
    if (i < n) g_count[i] = 0;
}

// ---------------------------------------------------------------- kernel 2
__global__ void hist_kernel(const int* __restrict__ rows, int E) {
    int e = blockIdx.x * blockDim.x + threadIdx.x;
    if (e < E) atomicAdd(&g_count[rows[e]], 1);
}

// ---------------------------------------------------------------- kernel 3
// One-block exclusive scan over g_count[0..n) -> g_start, g_cursor.
static constexpr int SCAN_THREADS = 1024;
static constexpr int SCAN_ITEMS   = 10;     // covers up to 10240 bins

__global__ __launch_bounds__(SCAN_THREADS) void scan_kernel(int n) {
    __shared__ int partial[SCAN_THREADS];
    int tid  = threadIdx.x;
    int base = tid * SCAN_ITEMS;

    int local[SCAN_ITEMS];
    int sum = 0;
    #pragma unroll
    for (int i = 0; i < SCAN_ITEMS; i++) {
        int idx = base + i;
        int c = (idx < n) ? g_count[idx] : 0;
        local[i] = sum;             // exclusive within this thread's chunk
        sum += c;
    }
    partial[tid] = sum;
    __syncthreads();

    // Hillis-Steele inclusive scan over per-thread sums
    for (int off = 1; off < SCAN_THREADS; off <<= 1) {
        int t = (tid >= off) ? partial[tid - off] : 0;
        __syncthreads();
        partial[tid] += t;
        __syncthreads();
    }

    int prefix = (tid > 0) ? partial[tid - 1] : 0;   // exclusive across threads
    #pragma unroll
    for (int i = 0; i < SCAN_ITEMS; i++) {
        int idx = base + i;
        if (idx < n) {
            int s = prefix + local[i];
            g_start[idx]  = s;
            g_cursor[idx] = s;
        }
    }
    if (tid == SCAN_THREADS - 1) g_start[n] = partial[SCAN_THREADS - 1];
}

// ---------------------------------------------------------------- kernel 4
__global__ void scatter_kernel(const int*   __restrict__ rows,
                               const int*   __restrict__ cols,
                               const float* __restrict__ vals,
                               int E) {
    int e = blockIdx.x * blockDim.x + threadIdx.x;
    if (e >= E) return;
    int r = rows[e];
    int pos = atomicAdd(&g_cursor[r], 1);
    g_pairs[pos] = make_uint2((unsigned)cols[e], __float_as_uint(vals[e]));
}

// ---------------------------------------------------------------- kernel 5
// Warp per row: lane owns one float4 (16B) chunk of the 512B output row.
__global__ __launch_bounds__(256) void spmm_csr_kernel(
    const float4* __restrict__ emb,    // [N, 32] float4
    float4*       __restrict__ out,    // [N, 32] float4
    int n)
{
    int warp = (blockIdx.x * blockDim.x + threadIdx.x) >> 5;
    int lane = threadIdx.x & 31;
    if (warp >= n) return;

    int j   = g_start[warp];
    int end = g_start[warp + 1];

    float4 acc = make_float4(0.f, 0.f, 0.f, 0.f);

    // Full 32-edge chunks: coalesced pair load, fully-unrolled shfl broadcast
    // so the 32 gather LDG.128s can be batched for MLP.
    while (end - j >= 32) {
        uint2 p = g_pairs[j + lane];
        #pragma unroll 8
        for (int k = 0; k < 32; k++) {
            int   c = __shfl_sync(0xffffffffu, (int)p.x, k);
            float v = __uint_as_float(__shfl_sync(0xffffffffu, p.y, k));
            float4 x = __ldg(emb + c * D_VEC + lane);
            acc.x += v * x.x; acc.y += v * x.y;
            acc.z += v * x.z; acc.w += v * x.w;
        }
        j += 32;
    }

    // Remainder
    int m = end - j;
    if (m > 0) {
        uint2 p = (lane < m) ? g_pairs[j + lane] : make_uint2(0u, 0u);
        for (int k = 0; k < m; k++) {
            int   c = __shfl_sync(0xffffffffu, (int)p.x, k);
            float v = __uint_as_float(__shfl_sync(0xffffffffu, p.y, k));
            float4 x = __ldg(emb + c * D_VEC + lane);
            acc.x += v * x.x; acc.y += v * x.y;
            acc.z += v * x.z; acc.w += v * x.w;
        }
    }

    out[warp * D_VEC + lane] = acc;   // rows with no edges write zeros
}

// ----------------------------------------------------------------- launch
extern "C" void kernel_launch(void* const* d_in, const int* in_sizes, int n_in,
                              void* d_out, int out_size) {
    const int*   adj_rows = (const int*)  d_in[0];
    const int*   adj_cols = (const int*)  d_in[1];
    const float* adj_vals = (const float*)d_in[2];
    const float* embeds   = (const float*)d_in[3];
    float*       out      = (float*)d_out;

    const int E = in_sizes[0];           // 640000
    const int N = out_size / 128;        // 10000

    zero_counts_kernel<<<(N + 255) / 256, 256>>>(N);
    hist_kernel<<<(E + 255) / 256, 256>>>(adj_rows, E);
    scan_kernel<<<1, SCAN_THREADS>>>(N);
    scatter_kernel<<<(E + 255) / 256, 256>>>(adj_rows, adj_cols, adj_vals, E);

    long long total_threads = (long long)N * 32;
    int blocks = (int)((total_threads + 255) / 256);
    spmm_csr_kernel<<<blocks, 256>>>((const float4*)embeds, (float4*)out, N);
}